// round 2
// baseline (speedup 1.0000x reference)
#include <cuda_runtime.h>
#include <cuda_bf16.h>
#include <math.h>
#include <stdint.h>

#define DD 1024
#define EE 8
#define NTOK 8192
#define NROW 16384
#define RPAD 17408
#define NKEY 64

// ------------------------ scratch (device globals) ------------------------
static __device__ __nv_bfloat16 g_w1h[EE*DD*DD];
static __device__ __nv_bfloat16 g_w1l[EE*DD*DD];
static __device__ __nv_bfloat16 g_w2h[EE*DD*DD];
static __device__ __nv_bfloat16 g_w2l[EE*DD*DD];
static __device__ float          g_xg[RPAD*DD];
static __device__ __nv_bfloat16 g_ah[RPAD*DD];
static __device__ __nv_bfloat16 g_al[RPAD*DD];
static __device__ __nv_bfloat16 g_hh[RPAD*DD];
static __device__ __nv_bfloat16 g_hl[RPAD*DD];
static __device__ float          g_y[RPAD*DD];
static __device__ float g_mu[RPAD];
static __device__ float g_rs[RPAD];
static __device__ float g_pre[NKEY*DD];
static __device__ int g_key[NROW];
static __device__ int g_rankloc[NROW];
static __device__ int g_histblk[16*NKEY];
static __device__ int g_blkoff[16*NKEY];
static __device__ int g_cnt[NKEY];
static __device__ int g_keystart[NKEY];
static __device__ int g_pstart[EE+1];
static __device__ int g_c2o[RPAD];

// ------------------------ helpers ------------------------
__device__ __forceinline__ void bsplit(float v, __nv_bfloat16& h, __nv_bfloat16& l) {
    h = __float2bfloat16(v);
    l = __float2bfloat16(v - __bfloat162float(h));
}
__device__ __forceinline__ float gelu_exact(float v) {
    return 0.5f * v * (1.0f + erff(v * 0.7071067811865475f));
}
__device__ __forceinline__ void ldsm4(uint32_t* r, const void* p) {
    uint32_t a = (uint32_t)__cvta_generic_to_shared(p);
    asm volatile("ldmatrix.sync.aligned.m8n8.x4.shared.b16 {%0,%1,%2,%3},[%4];"
                 : "=r"(r[0]), "=r"(r[1]), "=r"(r[2]), "=r"(r[3]) : "r"(a));
}
__device__ __forceinline__ void ldsm4t(uint32_t* r, const void* p) {
    uint32_t a = (uint32_t)__cvta_generic_to_shared(p);
    asm volatile("ldmatrix.sync.aligned.m8n8.x4.trans.shared.b16 {%0,%1,%2,%3},[%4];"
                 : "=r"(r[0]), "=r"(r[1]), "=r"(r[2]), "=r"(r[3]) : "r"(a));
}
__device__ __forceinline__ void mma16816(float* c, const uint32_t* a, const uint32_t* b) {
    asm volatile(
        "mma.sync.aligned.m16n8k16.row.col.f32.bf16.bf16.f32 "
        "{%0,%1,%2,%3},{%4,%5,%6,%7},{%8,%9},{%0,%1,%2,%3};"
        : "+f"(c[0]), "+f"(c[1]), "+f"(c[2]), "+f"(c[3])
        : "r"(a[0]), "r"(a[1]), "r"(a[2]), "r"(a[3]), "r"(b[0]), "r"(b[1]));
}
#define CP16(sm, gm) { uint32_t s_ = (uint32_t)__cvta_generic_to_shared(sm); \
    asm volatile("cp.async.cg.shared.global [%0],[%1],16;" :: "r"(s_), "l"(gm)); }

__device__ __forceinline__ float bsum(float v, float* red, int nw) {
    int lane = threadIdx.x & 31, w = threadIdx.x >> 5;
    #pragma unroll
    for (int o = 16; o; o >>= 1) v += __shfl_xor_sync(0xffffffffu, v, o);
    if (lane == 0) red[w] = v;
    __syncthreads();
    float r = 0.f;
    for (int i = 0; i < nw; i++) r += red[i];
    __syncthreads();
    return r;
}

// ------------------------ K0: convert W1/W2 to bf16 hi/lo ------------------------
__global__ void k_convert(const float* __restrict__ W1, const float* __restrict__ W2) {
    int i = blockIdx.x * 256 + threadIdx.x;       // 0 .. 2*T-1
    const int T = EE*DD*DD/4;
    const float* src; __nv_bfloat16* dh; __nv_bfloat16* dl; int j;
    if (i < T) { src = W1; dh = g_w1h; dl = g_w1l; j = i; }
    else       { src = W2; dh = g_w2h; dl = g_w2l; j = i - T; }
    float4 v = ((const float4*)src)[j];
    __nv_bfloat16 h0,l0,h1,l1,h2,l2,h3,l3;
    bsplit(v.x,h0,l0); bsplit(v.y,h1,l1); bsplit(v.z,h2,l2); bsplit(v.w,h3,l3);
    ((__nv_bfloat162*)dh)[j*2]   = __halves2bfloat162(h0,h1);
    ((__nv_bfloat162*)dh)[j*2+1] = __halves2bfloat162(h2,h3);
    ((__nv_bfloat162*)dl)[j*2]   = __halves2bfloat162(l0,l1);
    ((__nv_bfloat162*)dl)[j*2+1] = __halves2bfloat162(l2,l3);
}

// ------------------------ K1: gating (softmax top-2, jax tie semantics) ------------------------
__global__ void k_gate(const float* __restrict__ x, const float* __restrict__ Wg,
                       const float* __restrict__ bg) {
    int n = blockIdx.x * 4 + (threadIdx.x >> 5);
    int lane = threadIdx.x & 31;
    float s[8] = {0,0,0,0,0,0,0,0};
    for (int i = lane; i < DD; i += 32) {
        float xv = x[n*DD + i];
        #pragma unroll
        for (int e = 0; e < 8; e++) s[e] += xv * Wg[i*8 + e];
    }
    #pragma unroll
    for (int e = 0; e < 8; e++)
        #pragma unroll
        for (int o = 16; o; o >>= 1) s[e] += __shfl_xor_sync(0xffffffffu, s[e], o);
    if (lane == 0) {
        float m = -1e30f;
        #pragma unroll
        for (int e = 0; e < 8; e++) { s[e] += bg[e]; m = fmaxf(m, s[e]); }
        float p[8], sum = 0.f;
        #pragma unroll
        for (int e = 0; e < 8; e++) { p[e] = expf(s[e] - m); sum += p[e]; }
        #pragma unroll
        for (int e = 0; e < 8; e++) p[e] /= sum;
        int e1 = 0;
        #pragma unroll
        for (int e = 1; e < 8; e++) if (p[e] > p[e1]) e1 = e;
        int e2 = -1;
        #pragma unroll
        for (int e = 0; e < 8; e++) if (e != e1 && (e2 < 0 || p[e] > p[e2])) e2 = e;
        int b = n >> 10;
        g_key[2*n]   = e1*8 + b;
        g_key[2*n+1] = e2*8 + b;
    }
}

// ------------------------ K2: per-block stable rank + histogram ------------------------
__global__ void k_hist() {
    __shared__ int cnt[NKEY];
    int t = threadIdx.x;
    if (t < NKEY) cnt[t] = 0;
    __syncthreads();
    int r = blockIdx.x * 1024 + t;
    int k = g_key[r];
    int myrank = 0;
    for (int w = 0; w < 32; w++) {
        if ((t >> 5) == w) {
            int lane = t & 31;
            unsigned mask = __match_any_sync(0xffffffffu, k);
            unsigned lower = mask & ((1u << lane) - 1u);
            int leader = __ffs(mask) - 1;
            int base = 0;
            if (lane == leader) base = atomicAdd(&cnt[k], __popc(mask));
            base = __shfl_sync(mask, base, leader);
            myrank = base + __popc(lower);
        }
        __syncthreads();
    }
    g_rankloc[r] = myrank;
    if (t < NKEY) g_histblk[blockIdx.x * NKEY + t] = cnt[t];
}

// ------------------------ K3: scan (totals, padded starts, block offsets) ------------------------
__global__ void k_scan() {
    __shared__ int cs[NKEY];
    int t = threadIdx.x;  // 64 threads
    int c = 0;
    for (int blk = 0; blk < 16; blk++) c += g_histblk[blk*NKEY + t];
    cs[t] = c; g_cnt[t] = c;
    __syncthreads();
    if (t == 0) {
        int ps = 0;
        for (int e = 0; e < EE; e++) {
            g_pstart[e] = ps;
            int Re = 0;
            for (int b = 0; b < 8; b++) Re += cs[e*8 + b];
            ps += ((Re + 127) / 128) * 128;
        }
        g_pstart[EE] = ps;
        for (int e = 0; e < EE; e++) {
            int o = g_pstart[e];
            for (int b = 0; b < 8; b++) { g_keystart[e*8+b] = o; o += cs[e*8+b]; }
        }
    }
    __syncthreads();
    int o = g_keystart[t];
    for (int blk = 0; blk < 16; blk++) { g_blkoff[blk*NKEY + t] = o; o += g_histblk[blk*NKEY + t]; }
}

__global__ void k_fill() {
    int p = blockIdx.x * 256 + threadIdx.x;
    if (p < RPAD) g_c2o[p] = -1;
}

__global__ void k_scatter() {
    int r = blockIdx.x * 256 + threadIdx.x;
    int pos = g_blkoff[(r >> 10) * NKEY + g_key[r]] + g_rankloc[r];
    g_c2o[pos] = r;
}

// ------------------------ K4: gather xg = x + noise (sorted), split bf16 ------------------------
__global__ void k_gather(const float* __restrict__ x, const float* __restrict__ noise) {
    int p = blockIdx.x, t = threadIdx.x; // 256 threads
    int r = g_c2o[p];
    float4 v = make_float4(0.f, 0.f, 0.f, 0.f);
    if (r >= 0) {
        int n = r >> 1;
        float4 xv = ((const float4*)x)[n*256 + t];
        float4 nv = ((const float4*)noise)[r*256 + t];
        v = make_float4(xv.x+nv.x, xv.y+nv.y, xv.z+nv.z, xv.w+nv.w);
    }
    ((float4*)g_xg)[p*256 + t] = v;
    __nv_bfloat16 h0,l0,h1,l1,h2,l2,h3,l3;
    bsplit(v.x,h0,l0); bsplit(v.y,h1,l1); bsplit(v.z,h2,l2); bsplit(v.w,h3,l3);
    int j = p*256 + t;
    ((__nv_bfloat162*)g_ah)[j*2]   = __halves2bfloat162(h0,h1);
    ((__nv_bfloat162*)g_ah)[j*2+1] = __halves2bfloat162(h2,h3);
    ((__nv_bfloat162*)g_al)[j*2]   = __halves2bfloat162(l0,l1);
    ((__nv_bfloat162*)g_al)[j*2+1] = __halves2bfloat162(l2,l3);
}

// ------------------------ K5/K6: split-bf16 GEMM (128x128 tile, KD=16, double buffer) ------------------------
#define LOADSTAGE(KT, ST) { \
    int k0_ = (KT) * 16; \
    CP16(&As[ST][0][arow][acol], Agh + (row0+arow)*DD + k0_ + acol); \
    CP16(&As[ST][1][arow][acol], Agl + (row0+arow)*DD + k0_ + acol); \
    CP16(&Bs[ST][0][brow][bcol], Bgh + (k0_+brow)*DD + n0 + bcol); \
    CP16(&Bs[ST][1][brow][bcol], Bgl + (k0_+brow)*DD + n0 + bcol); \
    asm volatile("cp.async.commit_group;"); }

template<int PHASE>
__global__ void __launch_bounds__(256) k_gemm(const float* __restrict__ bias) {
    __shared__ __nv_bfloat16 As[2][2][128][24];
    __shared__ __nv_bfloat16 Bs[2][2][16][136];
    const int t = threadIdx.x;
    const int row0 = blockIdx.x * 128;
    if (row0 >= g_pstart[EE]) return;
    int e = 0;
    while (row0 >= g_pstart[e+1]) e++;
    const int n0 = blockIdx.y * 128;
    const __nv_bfloat16* Agh = (PHASE == 1) ? g_ah : g_hh;
    const __nv_bfloat16* Agl = (PHASE == 1) ? g_al : g_hl;
    const __nv_bfloat16* Bgh = ((PHASE == 1) ? g_w1h : g_w2h) + e*DD*DD;
    const __nv_bfloat16* Bgl = ((PHASE == 1) ? g_w1l : g_w2l) + e*DD*DD;

    const int arow = t >> 1,  acol = (t & 1) * 8;
    const int brow = t >> 4,  bcol = (t & 15) * 8;
    const int lane = t & 31, w = t >> 5;
    const int wm = w & 1, wn = w >> 1;
    const int lr = lane & 15, lc = (lane >> 4) * 8;

    float acc[4][4][4];
    #pragma unroll
    for (int i = 0; i < 4; i++)
        #pragma unroll
        for (int j = 0; j < 4; j++)
            #pragma unroll
            for (int q = 0; q < 4; q++) acc[i][j][q] = 0.f;

    LOADSTAGE(0, 0);
    for (int kt = 0; kt < 64; kt++) {
        asm volatile("cp.async.wait_group 0;");
        __syncthreads();
        if (kt < 63) LOADSTAGE(kt + 1, (kt + 1) & 1);
        int st = kt & 1;
        uint32_t ah[4][4], al[4][4], bh[2][4], bl[2][4];
        #pragma unroll
        for (int mt = 0; mt < 4; mt++) {
            ldsm4(ah[mt], &As[st][0][wm*64 + mt*16 + lr][lc]);
            ldsm4(al[mt], &As[st][1][wm*64 + mt*16 + lr][lc]);
        }
        #pragma unroll
        for (int ng = 0; ng < 2; ng++) {
            ldsm4t(bh[ng], &Bs[st][0][lr][wn*32 + ng*16 + lc]);
            ldsm4t(bl[ng], &Bs[st][1][lr][wn*32 + ng*16 + lc]);
        }
        #pragma unroll
        for (int mt = 0; mt < 4; mt++)
            #pragma unroll
            for (int ng = 0; ng < 2; ng++)
                #pragma unroll
                for (int hf = 0; hf < 2; hf++) {
                    int nt = ng*2 + hf;
                    mma16816(acc[mt][nt], ah[mt], &bh[ng][hf*2]);
                    mma16816(acc[mt][nt], ah[mt], &bl[ng][hf*2]);
                    mma16816(acc[mt][nt], al[mt], &bh[ng][hf*2]);
                }
        __syncthreads();
    }
    // epilogue
    #pragma unroll
    for (int mt = 0; mt < 4; mt++)
        #pragma unroll
        for (int nt = 0; nt < 4; nt++) {
            int row = row0 + wm*64 + mt*16 + (lane >> 2);
            int col = n0 + wn*32 + nt*8 + (lane & 3)*2;
            #pragma unroll
            for (int hf = 0; hf < 2; hf++) {
                int r2 = row + hf*8;
                float v0 = acc[mt][nt][hf*2 + 0];
                float v1 = acc[mt][nt][hf*2 + 1];
                if (PHASE == 1) {
                    v0 = gelu_exact(v0 + bias[e*DD + col]);
                    v1 = gelu_exact(v1 + bias[e*DD + col + 1]);
                    __nv_bfloat16 h0,l0,h1,l1;
                    bsplit(v0,h0,l0); bsplit(v1,h1,l1);
                    *(__nv_bfloat162*)(&g_hh[r2*DD + col]) = __halves2bfloat162(h0,h1);
                    *(__nv_bfloat162*)(&g_hl[r2*DD + col]) = __halves2bfloat162(l0,l1);
                } else {
                    float2 o;
                    o.x = v0 + bias[e*DD + col]     + g_xg[r2*DD + col];
                    o.y = v1 + bias[e*DD + col + 1] + g_xg[r2*DD + col + 1];
                    *(float2*)(&g_y[r2*DD + col]) = o;
                }
            }
        }
}

// ------------------------ K7: per-row LN stats ------------------------
__global__ void k_stats() {
    __shared__ float red[4];
    int p = blockIdx.x, t = threadIdx.x;  // 128 threads
    float v[8];
    #pragma unroll
    for (int i = 0; i < 8; i++) v[i] = g_y[p*DD + t + i*128];
    float s = 0.f;
    #pragma unroll
    for (int i = 0; i < 8; i++) s += v[i];
    s = bsum(s, red, 4);
    float mu = s * (1.f/1024.f);
    float q = 0.f;
    #pragma unroll
    for (int i = 0; i < 8; i++) { float d = v[i] - mu; q += d*d; }
    q = bsum(q, red, 4);
    if (t == 0) { g_mu[p] = mu; g_rs[p] = rsqrtf(q*(1.f/1024.f) + 1e-5f); }
}

// ------------------------ K8: deterministic segment reduction ------------------------
__global__ void k_reduce(const float* __restrict__ lng, const float* __restrict__ lnb) {
    int k = blockIdx.x;
    int d = blockIdx.y * 128 + threadIdx.x;
    int e = k >> 3, b = k & 7;
    int st = g_keystart[k], c = g_cnt[k];
    float s = 0.f;
    #pragma unroll 4
    for (int i = 0; i < c; i++) {
        int p = st + i;
        s += (g_y[p*DD + d] - g_mu[p]) * g_rs[p];
    }
    g_pre[(b*8 + e)*DD + d] = lng[e*DD + d] * s + (float)c * lnb[e*DD + d];
}

// ------------------------ K9: final LN ------------------------
__global__ void k_final(const float* __restrict__ gng, const float* __restrict__ gnb,
                        float* __restrict__ out) {
    __shared__ float red[8];
    int row = blockIdx.x, t = threadIdx.x;  // 256 threads
    float v[4];
    #pragma unroll
    for (int i = 0; i < 4; i++) v[i] = g_pre[row*DD + t + i*256];
    float s = 0.f;
    #pragma unroll
    for (int i = 0; i < 4; i++) s += v[i];
    s = bsum(s, red, 8);
    float mu = s * (1.f/1024.f);
    float q = 0.f;
    #pragma unroll
    for (int i = 0; i < 4; i++) { float d = v[i] - mu; q += d*d; }
    q = bsum(q, red, 8);
    float rs = rsqrtf(q*(1.f/1024.f) + 1e-5f);
    #pragma unroll
    for (int i = 0; i < 4; i++) {
        int d = t + i*256;
        out[row*DD + d] = (v[i] - mu) * rs * gng[d] + gnb[d];
    }
}

// ------------------------ launch ------------------------
extern "C" void kernel_launch(void* const* d_in, const int* in_sizes, int n_in,
                              void* d_out, int out_size) {
    const float* x     = (const float*)d_in[0];
    const float* noise = (const float*)d_in[1];
    const float* Wg    = (const float*)d_in[2];
    const float* bg    = (const float*)d_in[3];
    const float* W1    = (const float*)d_in[4];
    const float* b1    = (const float*)d_in[5];
    const float* W2    = (const float*)d_in[6];
    const float* b2    = (const float*)d_in[7];
    const float* lng   = (const float*)d_in[8];
    const float* lnb   = (const float*)d_in[9];
    const float* gng   = (const float*)d_in[10];
    const float* gnb   = (const float*)d_in[11];
    float* out = (float*)d_out;

    k_convert<<<16384, 256>>>(W1, W2);
    k_gate<<<NTOK/4, 128>>>(x, Wg, bg);
    k_hist<<<16, 1024>>>();
    k_scan<<<1, 64>>>();
    k_fill<<<RPAD/256, 256>>>();
    k_scatter<<<NROW/256, 256>>>();
    k_gather<<<RPAD, 256>>>(x, noise);
    k_gemm<1><<<dim3(RPAD/128, 8), 256>>>(b1);
    k_gemm<2><<<dim3(RPAD/128, 8), 256>>>(b2);
    k_stats<<<RPAD, 128>>>();
    k_reduce<<<dim3(NKEY, 8), 128>>>(lng, lnb);
    k_final<<<NKEY, 256>>>(gng, gnb, out);
}

// round 4
// speedup vs baseline: 1.1357x; 1.1357x over previous
#include <cuda_runtime.h>
#include <cuda_fp16.h>
#include <math.h>
#include <stdint.h>

#define DD 1024
#define EE 8
#define NTOK 8192
#define NROW 16384
#define RPAD 17408
#define NKEY 64

// ------------------------ scratch (device globals) ------------------------
static __device__ __align__(256) __half g_w1[(size_t)EE*DD*DD];   // fp16 [e][k][n]
static __device__ __align__(256) __half g_w2[(size_t)EE*DD*DD];   // fp16 [e][k][n]
static __device__ __align__(256) __half g_ah[(size_t)RPAD*DD];
static __device__ __align__(256) __half g_al[(size_t)RPAD*DD];
static __device__ __align__(256) __half g_hh[(size_t)RPAD*DD];
static __device__ __align__(256) __half g_hl[(size_t)RPAD*DD];
static __device__ __align__(256) float  g_y[(size_t)RPAD*DD];
static __device__ float g_mu[RPAD];
static __device__ float g_rs[RPAD];
static __device__ float g_pre[NKEY*DD];
static __device__ int g_key[NROW];
static __device__ int g_rankloc[NROW];
static __device__ int g_histblk[16*NKEY];
static __device__ int g_blkoff[16*NKEY];
static __device__ int g_cnt[NKEY];
static __device__ int g_keystart[NKEY];
static __device__ int g_pstart[EE+1];
static __device__ int g_c2o[RPAD];

// ------------------------ helpers ------------------------
__device__ __forceinline__ void hsplit(float v, __half& h, __half& l) {
    h = __float2half(v);
    l = __float2half(v - __half2float(h));
}
__device__ __forceinline__ float gelu_exact(float v) {
    return 0.5f * v * (1.0f + erff(v * 0.7071067811865475f));
}
__device__ __forceinline__ void ldsm4(uint32_t* r, const void* p) {
    uint32_t a = (uint32_t)__cvta_generic_to_shared(p);
    asm volatile("ldmatrix.sync.aligned.m8n8.x4.shared.b16 {%0,%1,%2,%3},[%4];"
                 : "=r"(r[0]), "=r"(r[1]), "=r"(r[2]), "=r"(r[3]) : "r"(a));
}
__device__ __forceinline__ void ldsm4t(uint32_t* r, const void* p) {
    uint32_t a = (uint32_t)__cvta_generic_to_shared(p);
    asm volatile("ldmatrix.sync.aligned.m8n8.x4.trans.shared.b16 {%0,%1,%2,%3},[%4];"
                 : "=r"(r[0]), "=r"(r[1]), "=r"(r[2]), "=r"(r[3]) : "r"(a));
}
__device__ __forceinline__ void mma16816(float* c, const uint32_t* a, const uint32_t* b) {
    asm volatile(
        "mma.sync.aligned.m16n8k16.row.col.f32.f16.f16.f32 "
        "{%0,%1,%2,%3},{%4,%5,%6,%7},{%8,%9},{%0,%1,%2,%3};"
        : "+f"(c[0]), "+f"(c[1]), "+f"(c[2]), "+f"(c[3])
        : "r"(a[0]), "r"(a[1]), "r"(a[2]), "r"(a[3]), "r"(b[0]), "r"(b[1]));
}
#define CP16(sm, gm) { uint32_t s_ = (uint32_t)__cvta_generic_to_shared(sm); \
    asm volatile("cp.async.cg.shared.global [%0],[%1],16;" :: "r"(s_), "l"(gm)); }

__device__ __forceinline__ float bsum(float v, float* red, int nw) {
    int lane = threadIdx.x & 31, w = threadIdx.x >> 5;
    #pragma unroll
    for (int o = 16; o; o >>= 1) v += __shfl_xor_sync(0xffffffffu, v, o);
    if (lane == 0) red[w] = v;
    __syncthreads();
    float r = 0.f;
    for (int i = 0; i < nw; i++) r += red[i];
    __syncthreads();
    return r;
}

// ------------------------ K0: convert W1/W2 to fp16 (elementwise, keep [k][n]) ------------------------
__global__ void k_convert(const float* __restrict__ W1, const float* __restrict__ W2) {
    int i = blockIdx.x * 256 + threadIdx.x;       // 0 .. 2*T-1, T in float4 units
    const int T = EE*DD*DD/4;
    const float* src; __half* dst; int j;
    if (i < T) { src = W1; dst = g_w1; j = i; }
    else       { src = W2; dst = g_w2; j = i - T; }
    float4 v = ((const float4*)src)[j];
    ((__half2*)dst)[j*2]   = __floats2half2_rn(v.x, v.y);
    ((__half2*)dst)[j*2+1] = __floats2half2_rn(v.z, v.w);
}

// ------------------------ K1: gating (softmax top-2, jax tie semantics) ------------------------
__global__ void k_gate(const float* __restrict__ x, const float* __restrict__ Wg,
                       const float* __restrict__ bg) {
    int n = blockIdx.x * 4 + (threadIdx.x >> 5);
    int lane = threadIdx.x & 31;
    float s[8] = {0,0,0,0,0,0,0,0};
    for (int i = lane; i < DD; i += 32) {
        float xv = x[n*DD + i];
        #pragma unroll
        for (int e = 0; e < 8; e++) s[e] += xv * Wg[i*8 + e];
    }
    #pragma unroll
    for (int e = 0; e < 8; e++)
        #pragma unroll
        for (int o = 16; o; o >>= 1) s[e] += __shfl_xor_sync(0xffffffffu, s[e], o);
    if (lane == 0) {
        float m = -1e30f;
        #pragma unroll
        for (int e = 0; e < 8; e++) { s[e] += bg[e]; m = fmaxf(m, s[e]); }
        float p[8], sum = 0.f;
        #pragma unroll
        for (int e = 0; e < 8; e++) { p[e] = expf(s[e] - m); sum += p[e]; }
        #pragma unroll
        for (int e = 0; e < 8; e++) p[e] /= sum;
        int e1 = 0;
        #pragma unroll
        for (int e = 1; e < 8; e++) if (p[e] > p[e1]) e1 = e;
        int e2 = -1;
        #pragma unroll
        for (int e = 0; e < 8; e++) if (e != e1 && (e2 < 0 || p[e] > p[e2])) e2 = e;
        int b = n >> 10;
        g_key[2*n]   = e1*8 + b;
        g_key[2*n+1] = e2*8 + b;
    }
}

// ------------------------ K2: per-block stable rank + histogram ------------------------
__global__ void k_hist() {
    __shared__ int cnt[NKEY];
    int t = threadIdx.x;
    if (t < NKEY) cnt[t] = 0;
    __syncthreads();
    int r = blockIdx.x * 1024 + t;
    int k = g_key[r];
    int myrank = 0;
    for (int w = 0; w < 32; w++) {
        if ((t >> 5) == w) {
            int lane = t & 31;
            unsigned mask = __match_any_sync(0xffffffffu, k);
            unsigned lower = mask & ((1u << lane) - 1u);
            int leader = __ffs(mask) - 1;
            int base = 0;
            if (lane == leader) base = atomicAdd(&cnt[k], __popc(mask));
            base = __shfl_sync(mask, base, leader);
            myrank = base + __popc(lower);
        }
        __syncthreads();
    }
    g_rankloc[r] = myrank;
    if (t < NKEY) g_histblk[blockIdx.x * NKEY + t] = cnt[t];
}

// ------------------------ K3: scan (totals, padded starts, block offsets) ------------------------
__global__ void k_scan() {
    __shared__ int cs[NKEY];
    int t = threadIdx.x;  // 64 threads
    int c = 0;
    for (int blk = 0; blk < 16; blk++) c += g_histblk[blk*NKEY + t];
    cs[t] = c; g_cnt[t] = c;
    __syncthreads();
    if (t == 0) {
        int ps = 0;
        for (int e = 0; e < EE; e++) {
            g_pstart[e] = ps;
            int Re = 0;
            for (int b = 0; b < 8; b++) Re += cs[e*8 + b];
            ps += ((Re + 127) / 128) * 128;
        }
        g_pstart[EE] = ps;
        for (int e = 0; e < EE; e++) {
            int o = g_pstart[e];
            for (int b = 0; b < 8; b++) { g_keystart[e*8+b] = o; o += cs[e*8+b]; }
        }
    }
    __syncthreads();
    int o = g_keystart[t];
    for (int blk = 0; blk < 16; blk++) { g_blkoff[blk*NKEY + t] = o; o += g_histblk[blk*NKEY + t]; }
}

__global__ void k_fill() {
    int p = blockIdx.x * 256 + threadIdx.x;
    if (p < RPAD) g_c2o[p] = -1;
}
__global__ void k_scatter() {
    int r = blockIdx.x * 256 + threadIdx.x;
    int pos = g_blkoff[(r >> 10) * NKEY + g_key[r]] + g_rankloc[r];
    g_c2o[pos] = r;
}

// ------------------------ K4: gather xg = x + noise (sorted), fp16 hi/lo ------------------------
__global__ void k_gather(const float* __restrict__ x, const float* __restrict__ noise) {
    int p = blockIdx.x, t = threadIdx.x; // 256 threads
    int r = g_c2o[p];
    float4 v = make_float4(0.f, 0.f, 0.f, 0.f);
    if (r >= 0) {
        int n = r >> 1;
        float4 xv = ((const float4*)x)[n*256 + t];
        float4 nv = ((const float4*)noise)[(size_t)r*256 + t];
        v = make_float4(xv.x+nv.x, xv.y+nv.y, xv.z+nv.z, xv.w+nv.w);
    }
    __half h0,l0,h1,l1,h2,l2,h3,l3;
    hsplit(v.x,h0,l0); hsplit(v.y,h1,l1); hsplit(v.z,h2,l2); hsplit(v.w,h3,l3);
    size_t j = (size_t)p*256 + t;
    ((__half2*)g_ah)[j*2]   = __halves2half2(h0,h1);
    ((__half2*)g_ah)[j*2+1] = __halves2half2(h2,h3);
    ((__half2*)g_al)[j*2]   = __halves2half2(l0,l1);
    ((__half2*)g_al)[j*2+1] = __halves2half2(l2,l3);
}

// ------------------------ K5/K6: fp16 2-product GEMM (128x128 tile, KD=16, double buffer) ------------------------
#define LOADSTAGE(KT, ST) { \
    int k0_ = (KT) * 16; \
    CP16(&As[ST][0][arow][acol], Agh + (size_t)(row0+arow)*DD + k0_ + acol); \
    CP16(&As[ST][1][arow][acol], Agl + (size_t)(row0+arow)*DD + k0_ + acol); \
    CP16(&Bs[ST][brow][bcol],    Bw  + (size_t)(k0_+brow)*DD + n0 + bcol); \
    asm volatile("cp.async.commit_group;"); }

template<int PHASE>
__global__ void __launch_bounds__(256, 2) k_gemm(const float* __restrict__ bias) {
    __shared__ __half As[2][2][128][24];
    __shared__ __half Bs[2][16][136];
    const int t = threadIdx.x;
    const int row0 = blockIdx.x * 128;
    if (row0 >= g_pstart[EE]) return;
    int e = 0;
    while (row0 >= g_pstart[e+1]) e++;
    const int n0 = blockIdx.y * 128;
    const __half* Agh = (PHASE == 1) ? g_ah : g_hh;
    const __half* Agl = (PHASE == 1) ? g_al : g_hl;
    const __half* Bw  = ((PHASE == 1) ? g_w1 : g_w2) + (size_t)e*DD*DD;

    const int arow = t >> 1,  acol = (t & 1) * 8;
    const int brow = t >> 4,  bcol = (t & 15) * 8;
    const int lane = t & 31, w = t >> 5;
    const int wm = w & 1, wn = w >> 1;
    const int lr = lane & 15, lc = (lane >> 4) * 8;

    float acc[4][4][4];
    #pragma unroll
    for (int i = 0; i < 4; i++)
        #pragma unroll
        for (int j = 0; j < 4; j++)
            #pragma unroll
            for (int q = 0; q < 4; q++) acc[i][j][q] = 0.f;

    LOADSTAGE(0, 0);
    for (int kt = 0; kt < 64; kt++) {
        asm volatile("cp.async.wait_group 0;" ::: "memory");
        __syncthreads();
        if (kt < 63) LOADSTAGE(kt + 1, (kt + 1) & 1);
        int st = kt & 1;
        uint32_t ah[4][4], al[4][4], bh[2][4];
        #pragma unroll
        for (int mt = 0; mt < 4; mt++) {
            ldsm4(ah[mt], &As[st][0][wm*64 + mt*16 + lr][lc]);
            ldsm4(al[mt], &As[st][1][wm*64 + mt*16 + lr][lc]);
        }
        #pragma unroll
        for (int ng = 0; ng < 2; ng++)
            ldsm4t(bh[ng], &Bs[st][lr][wn*32 + ng*16 + lc]);
        #pragma unroll
        for (int mt = 0; mt < 4; mt++)
            #pragma unroll
            for (int ng = 0; ng < 2; ng++)
                #pragma unroll
                for (int hf = 0; hf < 2; hf++) {
                    int nt = ng*2 + hf;
                    mma16816(acc[mt][nt], ah[mt], &bh[ng][hf*2]);
                    mma16816(acc[mt][nt], al[mt], &bh[ng][hf*2]);
                }
        __syncthreads();
    }
    // epilogue
    #pragma unroll
    for (int mt = 0; mt < 4; mt++)
        #pragma unroll
        for (int nt = 0; nt < 4; nt++) {
            int row = row0 + wm*64 + mt*16 + (lane >> 2);
            int col = n0 + wn*32 + nt*8 + (lane & 3)*2;
            #pragma unroll
            for (int hf = 0; hf < 2; hf++) {
                int r2 = row + hf*8;
                size_t gi = (size_t)r2*DD + col;
                float v0 = acc[mt][nt][hf*2 + 0];
                float v1 = acc[mt][nt][hf*2 + 1];
                float b0 = bias[e*DD + col], b1v = bias[e*DD + col + 1];
                if (PHASE == 1) {
                    v0 = gelu_exact(v0 + b0);
                    v1 = gelu_exact(v1 + b1v);
                    __half h0,l0,h1,l1;
                    hsplit(v0,h0,l0); hsplit(v1,h1,l1);
                    *(__half2*)(&g_hh[gi]) = __halves2half2(h0,h1);
                    *(__half2*)(&g_hl[gi]) = __halves2half2(l0,l1);
                } else {
                    __half2 a2 = *(const __half2*)(&g_ah[gi]);
                    __half2 l2 = *(const __half2*)(&g_al[gi]);
                    float2 o;
                    o.x = v0 + b0 + __half2float(__low2half(a2))  + __half2float(__low2half(l2));
                    o.y = v1 + b1v + __half2float(__high2half(a2)) + __half2float(__high2half(l2));
                    *(float2*)(&g_y[gi]) = o;
                }
            }
        }
}

// ------------------------ K7: per-row LN stats ------------------------
__global__ void k_stats() {
    __shared__ float red[4];
    int p = blockIdx.x, t = threadIdx.x;  // 128 threads
    float v[8];
    #pragma unroll
    for (int i = 0; i < 8; i++) v[i] = g_y[(size_t)p*DD + t + i*128];
    float s = 0.f;
    #pragma unroll
    for (int i = 0; i < 8; i++) s += v[i];
    s = bsum(s, red, 4);
    float mu = s * (1.f/1024.f);
    float q = 0.f;
    #pragma unroll
    for (int i = 0; i < 8; i++) { float d = v[i] - mu; q += d*d; }
    q = bsum(q, red, 4);
    if (t == 0) { g_mu[p] = mu; g_rs[p] = rsqrtf(q*(1.f/1024.f) + 1e-5f); }
}

// ------------------------ K8: deterministic segment reduction ------------------------
__global__ void k_reduce(const float* __restrict__ lng, const float* __restrict__ lnb) {
    int k = blockIdx.x;
    int d = blockIdx.y * 128 + threadIdx.x;
    int e = k >> 3, b = k & 7;
    int st = g_keystart[k], c = g_cnt[k];
    float s = 0.f;
    #pragma unroll 4
    for (int i = 0; i < c; i++) {
        int p = st + i;
        s += (g_y[(size_t)p*DD + d] - g_mu[p]) * g_rs[p];
    }
    g_pre[(b*8 + e)*DD + d] = lng[e*DD + d] * s + (float)c * lnb[e*DD + d];
}

// ------------------------ K9: final LN ------------------------
__global__ void k_final(const float* __restrict__ gng, const float* __restrict__ gnb,
                        float* __restrict__ out) {
    __shared__ float red[8];
    int row = blockIdx.x, t = threadIdx.x;  // 256 threads
    float v[4];
    #pragma unroll
    for (int i = 0; i < 4; i++) v[i] = g_pre[row*DD + t + i*256];
    float s = 0.f;
    #pragma unroll
    for (int i = 0; i < 4; i++) s += v[i];
    s = bsum(s, red, 8);
    float mu = s * (1.f/1024.f);
    float q = 0.f;
    #pragma unroll
    for (int i = 0; i < 4; i++) { float d = v[i] - mu; q += d*d; }
    q = bsum(q, red, 8);
    float rs = rsqrtf(q*(1.f/1024.f) + 1e-5f);
    #pragma unroll
    for (int i = 0; i < 4; i++) {
        int d = t + i*256;
        out[row*DD + d] = (v[i] - mu) * rs * gng[d] + gnb[d];
    }
}

// ------------------------ launch ------------------------
extern "C" void kernel_launch(void* const* d_in, const int* in_sizes, int n_in,
                              void* d_out, int out_size) {
    const float* x     = (const float*)d_in[0];
    const float* noise = (const float*)d_in[1];
    const float* Wg    = (const float*)d_in[2];
    const float* bg    = (const float*)d_in[3];
    const float* W1    = (const float*)d_in[4];
    const float* b1    = (const float*)d_in[5];
    const float* W2    = (const float*)d_in[6];
    const float* b2    = (const float*)d_in[7];
    const float* lng   = (const float*)d_in[8];
    const float* lnb   = (const float*)d_in[9];
    const float* gng   = (const float*)d_in[10];
    const float* gnb   = (const float*)d_in[11];
    float* out = (float*)d_out;

    k_convert<<<16384, 256>>>(W1, W2);
    k_gate<<<NTOK/4, 128>>>(x, Wg, bg);
    k_hist<<<16, 1024>>>();
    k_scan<<<1, 64>>>();
    k_fill<<<RPAD/256, 256>>>();
    k_scatter<<<NROW/256, 256>>>();
    k_gather<<<RPAD, 256>>>(x, noise);
    k_gemm<1><<<dim3(RPAD/128, 8), 256>>>(b1);
    k_gemm<2><<<dim3(RPAD/128, 8), 256>>>(b2);
    k_stats<<<RPAD, 128>>>();
    k_reduce<<<dim3(NKEY, 8), 128>>>(lng, lnb);
    k_final<<<NKEY, 256>>>(gng, gnb, out);
}

// round 5
// speedup vs baseline: 1.9422x; 1.7102x over previous
#include <cuda_runtime.h>
#include <cuda_fp16.h>
#include <math.h>
#include <stdint.h>

#define DD 1024
#define EE 8
#define NTOK 8192
#define NROW 16384
#define RPAD 17408
#define NKEY 64
#define GEMM_SMEM (3*(128*40 + 32*136)*2)

// ------------------------ scratch (device globals) ------------------------
static __device__ __align__(256) __half g_w1[(size_t)EE*DD*DD];   // fp16 [e][k][n]
static __device__ __align__(256) __half g_w2[(size_t)EE*DD*DD];   // fp16 [e][k][n]
static __device__ __align__(256) __half g_ah[(size_t)RPAD*DD];    // fp16 xg
static __device__ __align__(256) __half g_hh[(size_t)RPAD*DD];    // fp16 gelu(h)
static __device__ __align__(256) float  g_y[(size_t)RPAD*DD];     // fp32 xg, then y
static __device__ float g_mu[RPAD];
static __device__ float g_rs[RPAD];
static __device__ float g_pre[NKEY*DD];
static __device__ int g_key[NROW];
static __device__ int g_rankloc[NROW];
static __device__ int g_histblk[16*NKEY];
static __device__ int g_blkoff[16*NKEY];
static __device__ int g_cnt[NKEY];
static __device__ int g_keystart[NKEY];
static __device__ int g_pstart[EE+1];
static __device__ int g_c2o[RPAD];

// ------------------------ helpers ------------------------
__device__ __forceinline__ float gelu_exact(float v) {
    return 0.5f * v * (1.0f + erff(v * 0.7071067811865475f));
}
__device__ __forceinline__ void ldsm4(uint32_t* r, const void* p) {
    uint32_t a = (uint32_t)__cvta_generic_to_shared(p);
    asm volatile("ldmatrix.sync.aligned.m8n8.x4.shared.b16 {%0,%1,%2,%3},[%4];"
                 : "=r"(r[0]), "=r"(r[1]), "=r"(r[2]), "=r"(r[3]) : "r"(a));
}
__device__ __forceinline__ void ldsm4t(uint32_t* r, const void* p) {
    uint32_t a = (uint32_t)__cvta_generic_to_shared(p);
    asm volatile("ldmatrix.sync.aligned.m8n8.x4.trans.shared.b16 {%0,%1,%2,%3},[%4];"
                 : "=r"(r[0]), "=r"(r[1]), "=r"(r[2]), "=r"(r[3]) : "r"(a));
}
__device__ __forceinline__ void mma16816(float* c, const uint32_t* a, const uint32_t* b) {
    asm volatile(
        "mma.sync.aligned.m16n8k16.row.col.f32.f16.f16.f32 "
        "{%0,%1,%2,%3},{%4,%5,%6,%7},{%8,%9},{%0,%1,%2,%3};"
        : "+f"(c[0]), "+f"(c[1]), "+f"(c[2]), "+f"(c[3])
        : "r"(a[0]), "r"(a[1]), "r"(a[2]), "r"(a[3]), "r"(b[0]), "r"(b[1]));
}
#define CP16(sm, gm) { uint32_t s_ = (uint32_t)__cvta_generic_to_shared(sm); \
    asm volatile("cp.async.cg.shared.global [%0],[%1],16;" :: "r"(s_), "l"(gm)); }

__device__ __forceinline__ float bsum(float v, float* red, int nw) {
    int lane = threadIdx.x & 31, w = threadIdx.x >> 5;
    #pragma unroll
    for (int o = 16; o; o >>= 1) v += __shfl_xor_sync(0xffffffffu, v, o);
    if (lane == 0) red[w] = v;
    __syncthreads();
    float r = 0.f;
    for (int i = 0; i < nw; i++) r += red[i];
    __syncthreads();
    return r;
}

// ------------------------ K0: convert W1/W2 to fp16 ------------------------
__global__ void k_convert(const float* __restrict__ W1, const float* __restrict__ W2) {
    int i = blockIdx.x * 256 + threadIdx.x;
    const int T = EE*DD*DD/4;
    const float* src; __half* dst; int j;
    if (i < T) { src = W1; dst = g_w1; j = i; }
    else       { src = W2; dst = g_w2; j = i - T; }
    float4 v = ((const float4*)src)[j];
    ((__half2*)dst)[j*2]   = __floats2half2_rn(v.x, v.y);
    ((__half2*)dst)[j*2+1] = __floats2half2_rn(v.z, v.w);
}

// ------------------------ K1: gating ------------------------
__global__ void k_gate(const float* __restrict__ x, const float* __restrict__ Wg,
                       const float* __restrict__ bg) {
    int n = blockIdx.x * 4 + (threadIdx.x >> 5);
    int lane = threadIdx.x & 31;
    float s[8] = {0,0,0,0,0,0,0,0};
    for (int i = lane; i < DD; i += 32) {
        float xv = x[n*DD + i];
        #pragma unroll
        for (int e = 0; e < 8; e++) s[e] += xv * Wg[i*8 + e];
    }
    #pragma unroll
    for (int e = 0; e < 8; e++)
        #pragma unroll
        for (int o = 16; o; o >>= 1) s[e] += __shfl_xor_sync(0xffffffffu, s[e], o);
    if (lane == 0) {
        float m = -1e30f;
        #pragma unroll
        for (int e = 0; e < 8; e++) { s[e] += bg[e]; m = fmaxf(m, s[e]); }
        float p[8], sum = 0.f;
        #pragma unroll
        for (int e = 0; e < 8; e++) { p[e] = expf(s[e] - m); sum += p[e]; }
        #pragma unroll
        for (int e = 0; e < 8; e++) p[e] /= sum;
        int e1 = 0;
        #pragma unroll
        for (int e = 1; e < 8; e++) if (p[e] > p[e1]) e1 = e;
        int e2 = -1;
        #pragma unroll
        for (int e = 0; e < 8; e++) if (e != e1 && (e2 < 0 || p[e] > p[e2])) e2 = e;
        int b = n >> 10;
        g_key[2*n]   = e1*8 + b;
        g_key[2*n+1] = e2*8 + b;
    }
}

// ------------------------ K2: per-block stable rank + histogram ------------------------
__global__ void k_hist() {
    __shared__ int cnt[NKEY];
    int t = threadIdx.x;
    if (t < NKEY) cnt[t] = 0;
    __syncthreads();
    int r = blockIdx.x * 1024 + t;
    int k = g_key[r];
    int myrank = 0;
    for (int w = 0; w < 32; w++) {
        if ((t >> 5) == w) {
            int lane = t & 31;
            unsigned mask = __match_any_sync(0xffffffffu, k);
            unsigned lower = mask & ((1u << lane) - 1u);
            int leader = __ffs(mask) - 1;
            int base = 0;
            if (lane == leader) base = atomicAdd(&cnt[k], __popc(mask));
            base = __shfl_sync(mask, base, leader);
            myrank = base + __popc(lower);
        }
        __syncthreads();
    }
    g_rankloc[r] = myrank;
    if (t < NKEY) g_histblk[blockIdx.x * NKEY + t] = cnt[t];
}

// ------------------------ K3: scan ------------------------
__global__ void k_scan() {
    __shared__ int cs[NKEY];
    int t = threadIdx.x;  // 64 threads
    int c = 0;
    for (int blk = 0; blk < 16; blk++) c += g_histblk[blk*NKEY + t];
    cs[t] = c; g_cnt[t] = c;
    __syncthreads();
    if (t == 0) {
        int ps = 0;
        for (int e = 0; e < EE; e++) {
            g_pstart[e] = ps;
            int Re = 0;
            for (int b = 0; b < 8; b++) Re += cs[e*8 + b];
            ps += ((Re + 127) / 128) * 128;
        }
        g_pstart[EE] = ps;
        for (int e = 0; e < EE; e++) {
            int o = g_pstart[e];
            for (int b = 0; b < 8; b++) { g_keystart[e*8+b] = o; o += cs[e*8+b]; }
        }
    }
    __syncthreads();
    int o = g_keystart[t];
    for (int blk = 0; blk < 16; blk++) { g_blkoff[blk*NKEY + t] = o; o += g_histblk[blk*NKEY + t]; }
}

__global__ void k_fill() {
    int p = blockIdx.x * 256 + threadIdx.x;
    if (p < RPAD) g_c2o[p] = -1;
}
__global__ void k_scatter() {
    int r = blockIdx.x * 256 + threadIdx.x;
    int pos = g_blkoff[(r >> 10) * NKEY + g_key[r]] + g_rankloc[r];
    g_c2o[pos] = r;
}

// ------------------------ K4: gather xg = x + noise; fp16 copy + fp32 copy ------------------------
__global__ void k_gather(const float* __restrict__ x, const float* __restrict__ noise) {
    int p = blockIdx.x, t = threadIdx.x; // 256 threads
    int r = g_c2o[p];
    float4 v = make_float4(0.f, 0.f, 0.f, 0.f);
    if (r >= 0) {
        int n = r >> 1;
        float4 xv = ((const float4*)x)[n*256 + t];
        float4 nv = ((const float4*)noise)[(size_t)r*256 + t];
        v = make_float4(xv.x+nv.x, xv.y+nv.y, xv.z+nv.z, xv.w+nv.w);
    }
    size_t j = (size_t)p*256 + t;
    ((float4*)g_y)[j] = v;
    ((__half2*)g_ah)[j*2]   = __floats2half2_rn(v.x, v.y);
    ((__half2*)g_ah)[j*2+1] = __floats2half2_rn(v.z, v.w);
}

// ------------------------ K5/K6: fp16 GEMM 128x128, KD=32, 3-stage pipeline ------------------------
__device__ __forceinline__ void load_stage(__half (*As)[128][40], __half (*Bs)[32][136],
    int st, int kt, const __half* __restrict__ Ag, const __half* __restrict__ Bw,
    int row0, int n0, int t)
{
    const int k0 = kt * 32;
    #pragma unroll
    for (int i = 0; i < 2; i++) {
        int c = t + i * 256;
        int row = c >> 2, k8 = (c & 3) * 8;
        CP16(&As[st][row][k8], Ag + (size_t)(row0 + row) * DD + k0 + k8);
    }
    #pragma unroll
    for (int i = 0; i < 2; i++) {
        int c = t + i * 256;
        int brow = c >> 4, bc = (c & 15) * 8;
        CP16(&Bs[st][brow][bc], Bw + (size_t)(k0 + brow) * DD + n0 + bc);
    }
    asm volatile("cp.async.commit_group;" ::: "memory");
}

template<int PHASE>
__global__ void __launch_bounds__(256, 2) k_gemm(const float* __restrict__ bias) {
    extern __shared__ char smraw[];
    __half (*As)[128][40] = (__half (*)[128][40])smraw;
    __half (*Bs)[32][136] = (__half (*)[32][136])(smraw + 3 * 128 * 40 * 2);

    const int t = threadIdx.x;
    const int row0 = blockIdx.x * 128;
    if (row0 >= g_pstart[EE]) return;
    int e = 0;
    while (row0 >= g_pstart[e+1]) e++;
    const int n0 = blockIdx.y * 128;
    const __half* Ag = (PHASE == 1) ? g_ah : g_hh;
    const __half* Bw = ((PHASE == 1) ? g_w1 : g_w2) + (size_t)e*DD*DD;

    const int lane = t & 31, w = t >> 5;
    const int wm = w & 1, wn = w >> 1;
    const int lr = lane & 15, lc = (lane >> 4) * 8;

    float acc[4][4][4];
    #pragma unroll
    for (int i = 0; i < 4; i++)
        #pragma unroll
        for (int j = 0; j < 4; j++)
            #pragma unroll
            for (int q = 0; q < 4; q++) acc[i][j][q] = 0.f;

    load_stage(As, Bs, 0, 0, Ag, Bw, row0, n0, t);
    load_stage(As, Bs, 1, 1, Ag, Bw, row0, n0, t);

    int st = 0;
    for (int kt = 0; kt < 32; kt++) {
        if (kt < 31) asm volatile("cp.async.wait_group 1;" ::: "memory");
        else         asm volatile("cp.async.wait_group 0;" ::: "memory");
        __syncthreads();
        if (kt + 2 < 32) {
            int st2 = (st + 2 >= 3) ? st - 1 : st + 2;
            load_stage(As, Bs, st2, kt + 2, Ag, Bw, row0, n0, t);
        }
        #pragma unroll
        for (int k16 = 0; k16 < 2; k16++) {
            uint32_t a[4][4], b[2][4];
            #pragma unroll
            for (int mt = 0; mt < 4; mt++)
                ldsm4(a[mt], &As[st][wm*64 + mt*16 + lr][k16*16 + lc]);
            #pragma unroll
            for (int ng = 0; ng < 2; ng++)
                ldsm4t(b[ng], &Bs[st][k16*16 + lr][wn*32 + ng*16 + lc]);
            #pragma unroll
            for (int mt = 0; mt < 4; mt++)
                #pragma unroll
                for (int ng = 0; ng < 2; ng++)
                    #pragma unroll
                    for (int hf = 0; hf < 2; hf++)
                        mma16816(acc[mt][ng*2 + hf], a[mt], &b[ng][hf*2]);
        }
        __syncthreads();
        st++; if (st == 3) st = 0;
    }

    // epilogue
    #pragma unroll
    for (int mt = 0; mt < 4; mt++)
        #pragma unroll
        for (int nt = 0; nt < 4; nt++) {
            int row = row0 + wm*64 + mt*16 + (lane >> 2);
            int col = n0 + wn*32 + nt*8 + (lane & 3)*2;
            #pragma unroll
            for (int hf = 0; hf < 2; hf++) {
                int r2 = row + hf*8;
                size_t gi = (size_t)r2*DD + col;
                float v0 = acc[mt][nt][hf*2 + 0];
                float v1 = acc[mt][nt][hf*2 + 1];
                float b0 = bias[e*DD + col], b1v = bias[e*DD + col + 1];
                if (PHASE == 1) {
                    v0 = gelu_exact(v0 + b0);
                    v1 = gelu_exact(v1 + b1v);
                    *(__half2*)(&g_hh[gi]) = __floats2half2_rn(v0, v1);
                } else {
                    float2 xg = *(const float2*)(&g_y[gi]);
                    float2 o;
                    o.x = v0 + b0  + xg.x;
                    o.y = v1 + b1v + xg.y;
                    *(float2*)(&g_y[gi]) = o;
                }
            }
        }
}

// ------------------------ K7: per-row LN stats ------------------------
__global__ void k_stats() {
    __shared__ float red[4];
    int p = blockIdx.x, t = threadIdx.x;  // 128 threads
    float v[8];
    #pragma unroll
    for (int i = 0; i < 8; i++) v[i] = g_y[(size_t)p*DD + t + i*128];
    float s = 0.f;
    #pragma unroll
    for (int i = 0; i < 8; i++) s += v[i];
    s = bsum(s, red, 4);
    float mu = s * (1.f/1024.f);
    float q = 0.f;
    #pragma unroll
    for (int i = 0; i < 8; i++) { float d = v[i] - mu; q += d*d; }
    q = bsum(q, red, 4);
    if (t == 0) { g_mu[p] = mu; g_rs[p] = rsqrtf(q*(1.f/1024.f) + 1e-5f); }
}

// ------------------------ K8: deterministic segment reduction ------------------------
__global__ void k_reduce(const float* __restrict__ lng, const float* __restrict__ lnb) {
    int k = blockIdx.x;
    int d = blockIdx.y * 128 + threadIdx.x;
    int e = k >> 3, b = k & 7;
    int st = g_keystart[k], c = g_cnt[k];
    float s = 0.f;
    #pragma unroll 4
    for (int i = 0; i < c; i++) {
        int p = st + i;
        s += (g_y[(size_t)p*DD + d] - g_mu[p]) * g_rs[p];
    }
    g_pre[(b*8 + e)*DD + d] = lng[e*DD + d] * s + (float)c * lnb[e*DD + d];
}

// ------------------------ K9: final LN ------------------------
__global__ void k_final(const float* __restrict__ gng, const float* __restrict__ gnb,
                        float* __restrict__ out) {
    __shared__ float red[8];
    int row = blockIdx.x, t = threadIdx.x;  // 256 threads
    float v[4];
    #pragma unroll
    for (int i = 0; i < 4; i++) v[i] = g_pre[row*DD + t + i*256];
    float s = 0.f;
    #pragma unroll
    for (int i = 0; i < 4; i++) s += v[i];
    s = bsum(s, red, 8);
    float mu = s * (1.f/1024.f);
    float q = 0.f;
    #pragma unroll
    for (int i = 0; i < 4; i++) { float d = v[i] - mu; q += d*d; }
    q = bsum(q, red, 8);
    float rs = rsqrtf(q*(1.f/1024.f) + 1e-5f);
    #pragma unroll
    for (int i = 0; i < 4; i++) {
        int d = t + i*256;
        out[row*DD + d] = (v[i] - mu) * rs * gng[d] + gnb[d];
    }
}

// ------------------------ launch ------------------------
extern "C" void kernel_launch(void* const* d_in, const int* in_sizes, int n_in,
                              void* d_out, int out_size) {
    const float* x     = (const float*)d_in[0];
    const float* noise = (const float*)d_in[1];
    const float* Wg    = (const float*)d_in[2];
    const float* bg    = (const float*)d_in[3];
    const float* W1    = (const float*)d_in[4];
    const float* b1    = (const float*)d_in[5];
    const float* W2    = (const float*)d_in[6];
    const float* b2    = (const float*)d_in[7];
    const float* lng   = (const float*)d_in[8];
    const float* lnb   = (const float*)d_in[9];
    const float* gng   = (const float*)d_in[10];
    const float* gnb   = (const float*)d_in[11];
    float* out = (float*)d_out;

    cudaFuncSetAttribute(k_gemm<1>, cudaFuncAttributeMaxDynamicSharedMemorySize, GEMM_SMEM);
    cudaFuncSetAttribute(k_gemm<2>, cudaFuncAttributeMaxDynamicSharedMemorySize, GEMM_SMEM);

    k_convert<<<16384, 256>>>(W1, W2);
    k_gate<<<NTOK/4, 128>>>(x, Wg, bg);
    k_hist<<<16, 1024>>>();
    k_scan<<<1, 64>>>();
    k_fill<<<RPAD/256, 256>>>();
    k_scatter<<<NROW/256, 256>>>();
    k_gather<<<RPAD, 256>>>(x, noise);
    k_gemm<1><<<dim3(RPAD/128, 8), 256, GEMM_SMEM>>>(b1);
    k_gemm<2><<<dim3(RPAD/128, 8), 256, GEMM_SMEM>>>(b2);
    k_stats<<<RPAD, 128>>>();
    k_reduce<<<dim3(NKEY, 8), 128>>>(lng, lnb);
    k_final<<<NKEY, 256>>>(gng, gnb, out);
}